// round 2
// baseline (speedup 1.0000x reference)
#include <cuda_runtime.h>
#include <cuda_bf16.h>

// Problem constants
#define BATCH   4096
#define NOBST   128
#define VEH     18        // 2*6 + 6
#define OBD     4
#define F1      22        // VEH + OBD
#define H       256
#define OBSF    138
#define COMBF   396       // 138 + 256 + 2
#define TN      32        // obstacle tile
#define H1PAD   36        // padded row (multiple of 4 -> 16B aligned float4 rows)

__global__ __launch_bounds__(256)
void setq_fused_kernel(const float* __restrict__ obs,
                       const float* __restrict__ obstacles,
                       const float* __restrict__ act,
                       const float* __restrict__ ow1,
                       const float* __restrict__ ob1,
                       const float* __restrict__ ow2,
                       const float* __restrict__ ob2,
                       const float* __restrict__ qw1,
                       const float* __restrict__ qb1,
                       const float* __restrict__ qw2,
                       const float* __restrict__ qb2,
                       const float* __restrict__ qw3,
                       const float* __restrict__ qb3,
                       float* __restrict__ out)
{
    const int b = blockIdx.x;
    const int t = threadIdx.x;          // hidden channel 0..255

    __shared__ float obss[OBSF];        // full obs row (veh = obss[0..17])
    __shared__ float acts[2];
    __shared__ float masks[NOBST];
    __shared__ float obsts[OBD][TN];    // obstacle features for current tile
    __shared__ float h1s[H * H1PAD];    // h1 tile, layout [k][j], padded
    __shared__ float pooled[H];
    __shared__ float q1s[H];
    __shared__ float wsum[8];

    // ---- stage per-batch scalars ----
    if (t < OBSF)  obss[t]  = obs[b * OBSF + t];
    if (t < NOBST) masks[t] = obstacles[(b * 5 + 4) * NOBST + t];
    if (t < 2)     acts[t]  = act[b * 2 + t];
    __syncthreads();

    // ---- hoisted vehicle contribution to h1 channel t ----
    float base = ob1[t];
    #pragma unroll
    for (int f = 0; f < VEH; f++)
        base = fmaf(obss[f], ow1[f * H + t], base);
    const float w18 = ow1[(VEH + 0) * H + t];
    const float w19 = ow1[(VEH + 1) * H + t];
    const float w20 = ow1[(VEH + 2) * H + t];
    const float w21 = ow1[(VEH + 3) * H + t];
    const float ob2t = ob2[t];

    float pool = 0.f;

    // ---- obstacle MLP over 4 tiles of 32 ----
    for (int tile = 0; tile < NOBST / TN; tile++) {
        const int n0 = tile * TN;
        __syncthreads();   // previous tile's h1s reads done
        if (t < OBD * TN)
            obsts[t / TN][t % TN] =
                obstacles[(b * 5 + (t / TN)) * NOBST + n0 + (t % TN)];
        __syncthreads();

        // h1[t][j] for this tile: base + 4 obstacle-feature FMAs, relu
        #pragma unroll
        for (int j = 0; j < TN; j++) {
            float v = base;
            v = fmaf(w18, obsts[0][j], v);
            v = fmaf(w19, obsts[1][j], v);
            v = fmaf(w20, obsts[2][j], v);
            v = fmaf(w21, obsts[3][j], v);
            h1s[t * H1PAD + j] = fmaxf(v, 0.f);
        }
        __syncthreads();

        // h2 accumulation: acc[j] = sum_k h1[k][j] * ow2[k][t]
        float acc[TN];
        #pragma unroll
        for (int j = 0; j < TN; j++) acc[j] = 0.f;

        #pragma unroll 2
        for (int k = 0; k < H; k++) {
            const float w = ow2[k * H + t];               // coalesced, L1/L2 hit
            const float4* row = (const float4*)(h1s + k * H1PAD); // broadcast
            #pragma unroll
            for (int q = 0; q < 8; q++) {
                float4 a = row[q];
                acc[4 * q + 0] = fmaf(a.x, w, acc[4 * q + 0]);
                acc[4 * q + 1] = fmaf(a.y, w, acc[4 * q + 1]);
                acc[4 * q + 2] = fmaf(a.z, w, acc[4 * q + 2]);
                acc[4 * q + 3] = fmaf(a.w, w, acc[4 * q + 3]);
            }
        }

        // fused bias + relu + masked pooling (h2 never materialized)
        #pragma unroll
        for (int j = 0; j < TN; j++) {
            float h2 = fmaxf(acc[j] + ob2t, 0.f);
            pool = fmaf(masks[n0 + j], h2, pool);
        }
    }

    pooled[t] = pool;
    __syncthreads();

    // ---- Q head: q1 = relu(comb @ qw1 + qb1) ----
    float a1 = qb1[t];
    #pragma unroll 4
    for (int f = 0; f < OBSF; f++)
        a1 = fmaf(obss[f], qw1[f * H + t], a1);
    #pragma unroll 4
    for (int f = 0; f < H; f++)
        a1 = fmaf(pooled[f], qw1[(OBSF + f) * H + t], a1);
    a1 = fmaf(acts[0], qw1[(OBSF + H + 0) * H + t], a1);
    a1 = fmaf(acts[1], qw1[(OBSF + H + 1) * H + t], a1);
    q1s[t] = fmaxf(a1, 0.f);
    __syncthreads();

    // ---- q2 = relu(q1 @ qw2 + qb2) ----
    float a2 = qb2[t];
    #pragma unroll 4
    for (int k = 0; k < H; k++)
        a2 = fmaf(q1s[k], qw2[k * H + t], a2);
    a2 = fmaxf(a2, 0.f);

    // ---- q = q2 @ qw3 + qb3 : block reduction ----
    float part = a2 * qw3[t];
    #pragma unroll
    for (int o = 16; o > 0; o >>= 1)
        part += __shfl_down_sync(0xffffffffu, part, o);
    if ((t & 31) == 0) wsum[t >> 5] = part;
    __syncthreads();
    if (t == 0) {
        float s = qb3[0];
        #pragma unroll
        for (int i = 0; i < 8; i++) s += wsum[i];
        out[b] = s;
    }
}

extern "C" void kernel_launch(void* const* d_in, const int* in_sizes, int n_in,
                              void* d_out, int out_size)
{
    const float* obs       = (const float*)d_in[0];
    const float* obstacles = (const float*)d_in[1];
    const float* act       = (const float*)d_in[2];
    const float* ow1       = (const float*)d_in[3];
    const float* ob1       = (const float*)d_in[4];
    const float* ow2       = (const float*)d_in[5];
    const float* ob2       = (const float*)d_in[6];
    const float* qw1       = (const float*)d_in[7];
    const float* qb1       = (const float*)d_in[8];
    const float* qw2       = (const float*)d_in[9];
    const float* qb2       = (const float*)d_in[10];
    const float* qw3       = (const float*)d_in[11];
    const float* qb3       = (const float*)d_in[12];
    float* out             = (float*)d_out;

    setq_fused_kernel<<<BATCH, 256>>>(obs, obstacles, act,
                                      ow1, ob1, ow2, ob2,
                                      qw1, qb1, qw2, qb2, qw3, qb3,
                                      out);
}